// round 14
// baseline (speedup 1.0000x reference)
#include <cuda_runtime.h>
#include <math.h>

#define DD   1024
#define NH   16
#define HDIM 64
#define FF   2048
#define BB   8
#define EPSL 1e-5f
#define NC   32

typedef unsigned long long ull;

__device__ __forceinline__ ull pack2same(float v) {
    unsigned u = __float_as_uint(v);
    return ((ull)u << 32) | u;
}
#define FMA2(d, a, b) asm("fma.rn.f32x2 %0, %1, %2, %0;" : "+l"(d) : "l"(a), "l"(b))
#define ADD2(d, a, b) asm("add.rn.f32x2 %0, %1, %2;" : "=l"(d) : "l"(a), "l"(b))

__device__ float g_cstat[BB * NC * NH * 2];          // per-chunk (m, sum)
__device__ float g_qhat[NH * DD];
__device__ float g_qb[NH];
__device__ float g_ctxp[(size_t)BB * NC * NH * DD];  // unnormalized chunk ctx
__device__ float g_ctx[(size_t)BB * NH * DD];
__device__ float g_oattn[BB * DD];
__device__ float g_ores[BB * DD];
__device__ float g_h1[BB * DD];
__device__ float g_f[BB * FF];
__device__ float g_f2[BB * DD];

// ---------- q0 + qhat: grid (NH, 4) --------------------------------------------
__global__ void k_q0qhat(const float* __restrict__ Wqkv, const float* __restrict__ bqkv,
                         const float* __restrict__ cls) {
    int h = blockIdx.x, q = blockIdx.y;
    int t = threadIdx.x;                 // 256
    int w = t >> 5, lane = t & 31;
    __shared__ __align__(16) float clss[DD];
    __shared__ float q0s[HDIM];

    for (int i = t; i < DD / 4; i += 256)
        ((float4*)clss)[i] = ((const float4*)cls)[i];
    __syncthreads();

    const float4* c4 = (const float4*)clss;
    for (int jr = 0; jr < 8; jr++) {
        int j = w * 8 + jr;
        const float4* Wr = (const float4*)(Wqkv + (size_t)(h * HDIM + j) * DD);
        float acc = 0.f;
        for (int i = lane; i < DD / 4; i += 32) {
            float4 wv = Wr[i], cv = c4[i];
            acc += wv.x * cv.x + wv.y * cv.y + wv.z * cv.z + wv.w * cv.w;
        }
        #pragma unroll
        for (int o = 16; o; o >>= 1) acc += __shfl_xor_sync(0xffffffffu, acc, o);
        if (lane == 0) q0s[j] = acc + bqkv[h * HDIM + j];
    }
    __syncthreads();

    int d = q * 256 + t;
    float acc = 0.f;
    #pragma unroll 4
    for (int j = 0; j < HDIM; j++)
        acc += q0s[j] * Wqkv[(size_t)(DD + h * HDIM + j) * DD + d];
    g_qhat[h * DD + d] = acc;
    if (q == 0 && t == 0) {
        float s = 0.f;
        for (int j = 0; j < HDIM; j++) s += q0s[j] * bqkv[DD + h * HDIM + j];
        g_qb[h] = s;
    }
}

// ---------- FUSED scores + local-softmax + ctx: grid (NC, BB), block 512 ---------
#define ROWU 512
__global__ void __launch_bounds__(512, 2) k_sctx(
        const float* __restrict__ x, const float* __restrict__ y,
        const float* __restrict__ cls, const float* __restrict__ sep,
        const float* __restrict__ px, const float* __restrict__ py,
        const int* __restrict__ x_len, const int* __restrict__ y_len) {
    int c = blockIdx.x;
    int b = blockIdx.y;
    int t = threadIdx.x;           // 512
    int w = t >> 5, lane = t & 31;
    int lx = x_len[b], ly = y_len[b];
    int Sb = lx + ly + 3;
    int cl = (Sb + NC - 1) / NC;   // <= 33
    int s0 = c * cl, s1 = min(s0 + cl, Sb);
    int n  = s1 - s0;

    if (n <= 0) {
        #pragma unroll
        for (int h = 0; h < NH; h++)
            ((ull*)(g_ctxp + (((size_t)b * NC + c) * NH + h) * DD))[t] = 0ull;
        if (t < NH) {
            g_cstat[((b * NC + c) * NH + t) * 2]     = -1e30f;
            g_cstat[((b * NC + c) * NH + t) * 2 + 1] = 0.f;
        }
        return;
    }

    __shared__ float sc[36][NH];   // chunk scores [pos][head]
    __shared__ ull a2[NH][36];
    __shared__ float lm[NH];

    // ---- Phase B: scores. warp w = head w, iterates all chunk positions -------
    {
        int h = w;                 // 16 warps = 16 heads
        const float4* qr = (const float4*)(g_qhat + (size_t)h * DD);
        float qb = g_qb[h];
        for (int sp = 0; sp < n; sp++) {
            int s = s0 + sp;
            const float4* rp;
            const float4* pp = nullptr;
            if (s == 0)            rp = (const float4*)cls;
            else if (s <= lx)      { rp = (const float4*)(x + ((size_t)b * 512 + (s - 1)) * DD);
                                     pp = (const float4*)px; }
            else if (s == lx + 1 || s == lx + ly + 2) rp = (const float4*)sep;
            else                   { rp = (const float4*)(y + ((size_t)b * 512 + (s - lx - 2)) * DD);
                                     pp = (const float4*)py; }
            float acc = 0.f;
            #pragma unroll
            for (int k = 0; k < 8; k++) {
                float4 rv = __ldg(&rp[lane + 32 * k]);
                if (pp) {
                    float4 pv = __ldg(&pp[lane + 32 * k]);
                    rv.x += pv.x; rv.y += pv.y; rv.z += pv.z; rv.w += pv.w;
                }
                float4 qv = __ldg(&qr[lane + 32 * k]);
                acc += qv.x * rv.x + qv.y * rv.y + qv.z * rv.z + qv.w * rv.w;
            }
            #pragma unroll
            for (int o = 16; o; o >>= 1) acc += __shfl_xor_sync(0xffffffffu, acc, o);
            if (lane == 0) sc[sp][h] = (acc + qb) * 0.125f;
        }
    }
    __syncthreads();

    // ---- Phase C: local softmax stats ------------------------------------------
    if (t < NH) {
        int h = t;
        float m = -1e30f;
        for (int ss = 0; ss < n; ss++) m = fmaxf(m, sc[ss][h]);
        float sum = 0.f;
        for (int ss = 0; ss < n; ss++) sum += __expf(sc[ss][h] - m);
        lm[h] = m;
        g_cstat[((b * NC + c) * NH + h) * 2]     = m;
        g_cstat[((b * NC + c) * NH + h) * 2 + 1] = sum;
    }
    __syncthreads();
    for (int i = t; i < n * NH; i += 512) {
        int h = i & 15, ss = i >> 4;
        a2[h][ss] = pack2same(__expf(sc[ss][h] - lm[h]));
    }
    __syncthreads();

    // ---- Phase D: ctx accumulation, d2 = t covers all 1024 dims ------------------
    int d2 = t;
    ull acc[NH];
    #pragma unroll
    for (int h = 0; h < NH; h++) acc[h] = 0ull;

    if (s0 == 0) {
        ull cv = ((const ull*)cls)[d2];
        #pragma unroll
        for (int h = 0; h < NH; h++) FMA2(acc[h], a2[h][0], cv);
    }
    {
        int p0 = max(s0, 1), p1 = min(s1, lx + 1);
        if (p0 < p1) {
            ull pxv = ((const ull*)px)[d2];
            const ull* xp = (const ull*)x + ((size_t)b * 512 + (p0 - 1)) * ROWU + d2;
            int nn = p1 - p0, base = p0 - s0;
            int s = 0;
            for (; s + 2 <= nn; s += 2) {
                ull r0 = xp[(size_t)s * ROWU];
                ull r1 = xp[(size_t)(s + 1) * ROWU];
                ull v0, v1;
                ADD2(v0, r0, pxv);
                ADD2(v1, r1, pxv);
                int ss = base + s;
                #pragma unroll
                for (int h = 0; h < NH; h++) {
                    FMA2(acc[h], a2[h][ss], v0);
                    FMA2(acc[h], a2[h][ss + 1], v1);
                }
            }
            if (s < nn) {
                ull r0 = xp[(size_t)s * ROWU];
                ull v0;
                ADD2(v0, r0, pxv);
                int ss = base + s;
                #pragma unroll
                for (int h = 0; h < NH; h++) FMA2(acc[h], a2[h][ss], v0);
            }
        }
    }
    {
        int sA = lx + 1, sB = lx + ly + 2;
        bool hA = (sA >= s0 && sA < s1), hB = (sB >= s0 && sB < s1);
        if (hA || hB) {
            ull sv = ((const ull*)sep)[d2];
            if (hA) {
                #pragma unroll
                for (int h = 0; h < NH; h++) FMA2(acc[h], a2[h][sA - s0], sv);
            }
            if (hB) {
                #pragma unroll
                for (int h = 0; h < NH; h++) FMA2(acc[h], a2[h][sB - s0], sv);
            }
        }
    }
    {
        int p0 = max(s0, lx + 2), p1 = min(s1, lx + ly + 2);
        if (p0 < p1) {
            ull pyv = ((const ull*)py)[d2];
            const ull* yp = (const ull*)y + ((size_t)b * 512 + (p0 - lx - 2)) * ROWU + d2;
            int nn = p1 - p0, base = p0 - s0;
            int s = 0;
            for (; s + 2 <= nn; s += 2) {
                ull r0 = yp[(size_t)s * ROWU];
                ull r1 = yp[(size_t)(s + 1) * ROWU];
                ull v0, v1;
                ADD2(v0, r0, pyv);
                ADD2(v1, r1, pyv);
                int ss = base + s;
                #pragma unroll
                for (int h = 0; h < NH; h++) {
                    FMA2(acc[h], a2[h][ss], v0);
                    FMA2(acc[h], a2[h][ss + 1], v1);
                }
            }
            if (s < nn) {
                ull r0 = yp[(size_t)s * ROWU];
                ull v0;
                ADD2(v0, r0, pyv);
                int ss = base + s;
                #pragma unroll
                for (int h = 0; h < NH; h++) FMA2(acc[h], a2[h][ss], v0);
            }
        }
    }
    #pragma unroll
    for (int h = 0; h < NH; h++)
        ((ull*)(g_ctxp + (((size_t)b * NC + c) * NH + h) * DD))[d2] = acc[h];
}

// ---------- combine chunks (flash rescale): grid (BB, 32), block 256 --------------
__global__ void k_combine() {
    int b = blockIdx.x;
    int q = blockIdx.y;            // 0..31
    int t = threadIdx.x;           // 256
    int half = t >> 7;             // 0/1 -> chunk half
    int tt = t & 127;
    int j = q * 128 + tt;          // float4 index over NH*DD/4 = 4096
    int h = j >> 8;
    __shared__ float wsc[NC][NH];
    __shared__ float Ms[NH], inv[NH];
    __shared__ __align__(16) float4 buf[128];

    if (t < NH) {
        float M = -1e30f;
        for (int c = 0; c < NC; c++)
            M = fmaxf(M, g_cstat[((b * NC + c) * NH + t) * 2]);
        Ms[t] = M;
    }
    __syncthreads();
    if (t < NH) {
        float den = 0.f;
        for (int c = 0; c < NC; c++)
            den += g_cstat[((b * NC + c) * NH + t) * 2 + 1] *
                   __expf(g_cstat[((b * NC + c) * NH + t) * 2] - Ms[t]);
        inv[t] = 1.f / den;
    }
    __syncthreads();
    for (int i = t; i < NC * NH; i += 256) {
        int cc = i >> 4, hh = i & 15;
        wsc[cc][hh] = __expf(g_cstat[((b * NC + cc) * NH + hh) * 2] - Ms[hh]) * inv[hh];
    }
    __syncthreads();

    float4 s = {0.f, 0.f, 0.f, 0.f};
    int c0 = half * 16;
    #pragma unroll
    for (int cc = 0; cc < 16; cc++) {
        int c = c0 + cc;
        float4 v = ((const float4*)(g_ctxp + ((size_t)b * NC + c) * (NH * DD)))[j];
        float f = wsc[c][h];
        s.x += v.x * f; s.y += v.y * f; s.z += v.z * f; s.w += v.w * f;
    }
    if (half == 1) buf[tt] = s;
    __syncthreads();
    if (half == 0) {
        float4 o = buf[tt];
        s.x += o.x; s.y += o.y; s.z += o.z; s.w += o.w;
        ((float4*)(g_ctx + (size_t)b * (NH * DD)))[j] = s;
    }
}

// ---------- V projection ------------------------------------------------------------
__global__ void k_gemvV(const float* __restrict__ Wqkv, const float* __restrict__ bqkv) {
    __shared__ __align__(16) float xs[BB * DD];
    int t = threadIdx.x;           // 256
    int w = t >> 5, lane = t & 31;
    int e = blockIdx.x * 8 + w;
    int h = (blockIdx.x * 8) >> 6;

    float4* xs4 = (float4*)xs;
    for (int i = t; i < BB * DD / 4; i += 256) {
        int b = i >> 8, j4 = i & 255;
        xs4[i] = ((const float4*)(g_ctx + ((size_t)b * NH + h) * DD))[j4];
    }
    __syncthreads();

    const float4* Wr = (const float4*)(Wqkv + (size_t)(2 * DD + e) * DD);
    float acc[BB];
    #pragma unroll
    for (int b = 0; b < BB; b++) acc[b] = 0.f;
    for (int i = lane; i < DD / 4; i += 32) {
        float4 wv = Wr[i];
        #pragma unroll
        for (int b = 0; b < BB; b++) {
            float4 x4 = xs4[b * 256 + i];
            acc[b] += wv.x * x4.x + wv.y * x4.y + wv.z * x4.z + wv.w * x4.w;
        }
    }
    #pragma unroll
    for (int b = 0; b < BB; b++) {
        #pragma unroll
        for (int o = 16; o; o >>= 1)
            acc[b] += __shfl_xor_sync(0xffffffffu, acc[b], o);
    }
    if (lane == 0) {
        float be = bqkv[2 * DD + e];
        #pragma unroll
        for (int b = 0; b < BB; b++)
            g_oattn[(size_t)b * DD + e] = acc[b] + be;
    }
}

// ---------- batch-shared GEMV, optional fused input-LN --------------------------------
__global__ void k_gemv8(const float* __restrict__ W, const float* __restrict__ xin,
                        const float* __restrict__ bias, const float* __restrict__ residE,
                        const float* __restrict__ residB, float* __restrict__ out,
                        int IN, int OUT, int doRelu,
                        int doLN, const float* __restrict__ lng, const float* __restrict__ lnb,
                        float* __restrict__ h1out) {
    __shared__ __align__(16) float xs[BB * 1024];
    __shared__ __align__(16) float gs[1024], bs[1024];
    int t = threadIdx.x;           // 256
    int w = t >> 5, lane = t & 31;
    int e = blockIdx.x * 8 + w;

    float acc[BB];
    #pragma unroll
    for (int b = 0; b < BB; b++) acc[b] = 0.f;

    float4* xs4 = (float4*)xs;
    int nchunk = IN >> 10;
    for (int kc = 0; kc < nchunk; kc++) {
        for (int i = t; i < BB * 256; i += 256) {
            int b = i >> 8, j4 = i & 255;
            xs4[i] = ((const float4*)(xin + (size_t)b * IN + kc * 1024))[j4];
        }
        if (doLN) {
            if (t < 256) { ((float4*)gs)[t] = ((const float4*)lng)[t]; ((float4*)bs)[t] = ((const float4*)lnb)[t]; }
            __syncthreads();
            float* row = xs + w * 1024;
            float s = 0.f;
            #pragma unroll
            for (int j = 0; j < 32; j++) s += row[lane + 32 * j];
            #pragma unroll
            for (int o = 16; o; o >>= 1) s += __shfl_xor_sync(0xffffffffu, s, o);
            float m = s * (1.f / 1024.f);
            float v = 0.f;
            #pragma unroll
            for (int j = 0; j < 32; j++) { float dd2 = row[lane + 32 * j] - m; v += dd2 * dd2; }
            #pragma unroll
            for (int o = 16; o; o >>= 1) v += __shfl_xor_sync(0xffffffffu, v, o);
            float r = rsqrtf(v * (1.f / 1024.f) + EPSL);
            #pragma unroll
            for (int j = 0; j < 32; j++) {
                int idx = lane + 32 * j;
                row[idx] = (row[idx] - m) * r * gs[idx] + bs[idx];
            }
            __syncthreads();
            if (h1out && blockIdx.x == 0) {
                for (int i = t; i < BB * 256; i += 256)
                    ((float4*)h1out)[i] = xs4[i];
            }
        } else {
            __syncthreads();
        }
        const float4* Wr = (const float4*)(W + (size_t)e * IN + kc * 1024);
        for (int i = lane; i < 256; i += 32) {
            float4 wv = Wr[i];
            #pragma unroll
            for (int b = 0; b < BB; b++) {
                float4 x4 = xs4[b * 256 + i];
                acc[b] += wv.x * x4.x + wv.y * x4.y + wv.z * x4.z + wv.w * x4.w;
            }
        }
        __syncthreads();
    }
    #pragma unroll
    for (int b = 0; b < BB; b++) {
        #pragma unroll
        for (int o = 16; o; o >>= 1)
            acc[b] += __shfl_xor_sync(0xffffffffu, acc[b], o);
    }
    if (lane == 0) {
        float be = (bias ? bias[e] : 0.f) + (residE ? residE[e] : 0.f);
        #pragma unroll
        for (int b = 0; b < BB; b++) {
            float v = acc[b] + be;
            if (residB) v += residB[(size_t)b * OUT + e];
            if (doRelu) v = fmaxf(v, 0.f);
            out[(size_t)b * OUT + e] = v;
        }
    }
}

// ---------- LayerNorm ------------------------------------------------------------------
__global__ void k_ln(const float* __restrict__ in, const float* __restrict__ gamma,
                     const float* __restrict__ beta, float* __restrict__ out) {
    int b = blockIdx.x, t = threadIdx.x;  // 256
    const float* row = in + (size_t)b * DD;
    __shared__ float sred[8];
    __shared__ float smv[2];

    float s = 0.f;
    for (int i = t; i < DD; i += 256) s += row[i];
    #pragma unroll
    for (int o = 16; o; o >>= 1) s += __shfl_xor_sync(0xffffffffu, s, o);
    if ((t & 31) == 0) sred[t >> 5] = s;
    __syncthreads();
    if (t == 0) {
        float m = 0.f;
        #pragma unroll
        for (int i = 0; i < 8; i++) m += sred[i];
        smv[0] = m * (1.f / DD);
    }
    __syncthreads();
    float m = smv[0];

    float v = 0.f;
    for (int i = t; i < DD; i += 256) { float dd2 = row[i] - m; v += dd2 * dd2; }
    #pragma unroll
    for (int o = 16; o; o >>= 1) v += __shfl_xor_sync(0xffffffffu, v, o);
    __syncthreads();
    if ((t & 31) == 0) sred[t >> 5] = v;
    __syncthreads();
    if (t == 0) {
        float vv = 0.f;
        #pragma unroll
        for (int i = 0; i < 8; i++) vv += sred[i];
        smv[1] = rsqrtf(vv * (1.f / DD) + EPSL);
    }
    __syncthreads();
    float r = smv[1];
    for (int i = t; i < DD; i += 256)
        out[(size_t)b * DD + i] = (row[i] - m) * r * gamma[i] + beta[i];
}

extern "C" void kernel_launch(void* const* d_in, const int* in_sizes, int n_in,
                              void* d_out, int out_size) {
    const float* x     = (const float*)d_in[0];
    const float* y     = (const float*)d_in[1];
    const float* cls   = (const float*)d_in[2];
    const float* sep   = (const float*)d_in[3];
    const float* px    = (const float*)d_in[4];
    const float* py    = (const float*)d_in[5];
    const float* Wqkv  = (const float*)d_in[6];
    const float* bqkv  = (const float*)d_in[7];
    const float* Wo    = (const float*)d_in[8];
    const float* bo    = (const float*)d_in[9];
    const float* W1    = (const float*)d_in[10];
    const float* b1    = (const float*)d_in[11];
    const float* W2    = (const float*)d_in[12];
    const float* b2    = (const float*)d_in[13];
    const float* ln1g  = (const float*)d_in[14];
    const float* ln1b  = (const float*)d_in[15];
    const float* ln2g  = (const float*)d_in[16];
    const float* ln2b  = (const float*)d_in[17];
    const int*   x_len = (const int*)d_in[18];
    const int*   y_len = (const int*)d_in[19];
    float* outp = (float*)d_out;

    float *p_oattn, *p_ores, *p_h1, *p_f, *p_f2;
    cudaGetSymbolAddress((void**)&p_oattn, g_oattn);
    cudaGetSymbolAddress((void**)&p_ores,  g_ores);
    cudaGetSymbolAddress((void**)&p_h1,    g_h1);
    cudaGetSymbolAddress((void**)&p_f,     g_f);
    cudaGetSymbolAddress((void**)&p_f2,    g_f2);

    k_q0qhat<<<dim3(NH, 4), 256>>>(Wqkv, bqkv, cls);
    k_sctx<<<dim3(NC, BB), 512>>>(x, y, cls, sep, px, py, x_len, y_len);
    k_combine<<<dim3(BB, 32), 256>>>();
    k_gemvV<<<DD / 8, 256>>>(Wqkv, bqkv);
    k_gemv8<<<DD / 8, 256>>>(Wo, p_oattn, bo, cls, nullptr, p_ores, DD, DD, 0,
                             0, nullptr, nullptr, nullptr);
    k_gemv8<<<FF / 8, 256>>>(W1, p_ores, b1, nullptr, nullptr, p_f, DD, FF, 1,
                             1, ln1g, ln1b, p_h1);
    k_gemv8<<<DD / 8, 256>>>(W2, p_f, b2, nullptr, p_h1, p_f2, FF, DD, 0,
                             0, nullptr, nullptr, nullptr);
    k_ln<<<BB, 256>>>(p_f2, ln2g, ln2b, outp);
}

// round 15
// speedup vs baseline: 1.2281x; 1.2281x over previous
#include <cuda_runtime.h>
#include <math.h>

#define DD   1024
#define NH   16
#define HDIM 64
#define FF   2048
#define BB   8
#define SP   1056
#define EPSL 1e-5f
#define NC   32

typedef unsigned long long ull;

__device__ __forceinline__ ull pack2same(float v) {
    unsigned u = __float_as_uint(v);
    return ((ull)u << 32) | u;
}
#define FMA2(d, a, b) asm("fma.rn.f32x2 %0, %1, %2, %0;" : "+l"(d) : "l"(a), "l"(b))
#define ADD2(d, a, b) asm("add.rn.f32x2 %0, %1, %2;" : "=l"(d) : "l"(a), "l"(b))

__device__ float g_scores[(size_t)BB * NH * SP];
__device__ float g_cstat[BB * NC * NH * 2];
__device__ float g_qhat[NH * DD];
__device__ float g_qb[NH];
__device__ float g_ctxp[(size_t)BB * NC * NH * DD];
__device__ float g_ctx[(size_t)BB * NH * DD];
__device__ float g_oattn[BB * DD];
__device__ float g_ores[BB * DD];
__device__ float g_h1[BB * DD];
__device__ float g_f[BB * FF];
__device__ float g_f2[BB * DD];

// ---------- q0 + qhat: grid (NH, 4) --------------------------------------------
__global__ void k_q0qhat(const float* __restrict__ Wqkv, const float* __restrict__ bqkv,
                         const float* __restrict__ cls) {
    int h = blockIdx.x, q = blockIdx.y;
    int t = threadIdx.x;                 // 256
    int w = t >> 5, lane = t & 31;
    __shared__ __align__(16) float clss[DD];
    __shared__ float q0s[HDIM];

    for (int i = t; i < DD / 4; i += 256)
        ((float4*)clss)[i] = ((const float4*)cls)[i];
    __syncthreads();

    const float4* c4 = (const float4*)clss;
    for (int jr = 0; jr < 8; jr++) {
        int j = w * 8 + jr;
        const float4* Wr = (const float4*)(Wqkv + (size_t)(h * HDIM + j) * DD);
        float acc = 0.f;
        for (int i = lane; i < DD / 4; i += 32) {
            float4 wv = Wr[i], cv = c4[i];
            acc += wv.x * cv.x + wv.y * cv.y + wv.z * cv.z + wv.w * cv.w;
        }
        #pragma unroll
        for (int o = 16; o; o >>= 1) acc += __shfl_xor_sync(0xffffffffu, acc, o);
        if (lane == 0) q0s[j] = acc + bqkv[h * HDIM + j];
    }
    __syncthreads();

    int d = q * 256 + t;
    float acc = 0.f;
    #pragma unroll 4
    for (int j = 0; j < HDIM; j++)
        acc += q0s[j] * Wqkv[(size_t)(DD + h * HDIM + j) * DD + d];
    g_qhat[h * DD + d] = acc;
    if (q == 0 && t == 0) {
        float s = 0.f;
        for (int j = 0; j < HDIM; j++) s += q0s[j] * bqkv[DD + h * HDIM + j];
        g_qb[h] = s;
    }
}

// ---------- position fetch helper -----------------------------------------------
__device__ __forceinline__ void fetch_pos(
    int s, int lx, int ly, int b, int lane,
    const float* __restrict__ x, const float* __restrict__ y,
    const float* __restrict__ cls, const float* __restrict__ sep,
    const float4* __restrict__ pxs4, const float4* __restrict__ pys4,
    float4 v[8]) {
    if (s == 0) {
        const float4* c4 = (const float4*)cls;
        #pragma unroll
        for (int k = 0; k < 8; k++) v[k] = __ldg(&c4[lane + 32 * k]);
    } else if (s <= lx) {
        const float4* xr = (const float4*)(x + ((size_t)b * 512 + (s - 1)) * DD);
        #pragma unroll
        for (int k = 0; k < 8; k++) {
            float4 a = __ldg(&xr[lane + 32 * k]), p = pxs4[lane + 32 * k];
            v[k].x = a.x + p.x; v[k].y = a.y + p.y; v[k].z = a.z + p.z; v[k].w = a.w + p.w;
        }
    } else if (s == lx + 1 || s == lx + ly + 2) {
        const float4* s4 = (const float4*)sep;
        #pragma unroll
        for (int k = 0; k < 8; k++) v[k] = __ldg(&s4[lane + 32 * k]);
    } else {
        const float4* yr = (const float4*)(y + ((size_t)b * 512 + (s - lx - 2)) * DD);
        #pragma unroll
        for (int k = 0; k < 8; k++) {
            float4 a = __ldg(&yr[lane + 32 * k]), p = pys4[lane + 32 * k];
            v[k].x = a.x + p.x; v[k].y = a.y + p.y; v[k].z = a.z + p.z; v[k].w = a.w + p.w;
        }
    }
}

// ---------- scores: 2 positions/warp, grid (19, BB) ------------------------------
__global__ void k_scores(const float* __restrict__ x, const float* __restrict__ y,
                         const float* __restrict__ cls, const float* __restrict__ sep,
                         const float* __restrict__ px, const float* __restrict__ py,
                         const int* __restrict__ x_len, const int* __restrict__ y_len) {
    extern __shared__ __align__(16) float dsm[];
    float* qh  = dsm;
    float* pxs = dsm + NH * DD;
    float* pys = pxs + DD;
    float* qbs = pys + DD;
    int b = blockIdx.y;
    int t = threadIdx.x, w = t >> 5, lane = t & 31;

    float4* qh4 = (float4*)qh;
    for (int i = t; i < NH * DD / 4; i += 256) qh4[i] = ((const float4*)g_qhat)[i];
    if (t < 256) { ((float4*)pxs)[t] = ((const float4*)px)[t]; ((float4*)pys)[t] = ((const float4*)py)[t]; }
    if (t < NH) qbs[t] = g_qb[t];
    __syncthreads();

    int lx = x_len[b], ly = y_len[b];
    int Sb = lx + ly + 3;
    const float4* pxs4 = (const float4*)pxs;
    const float4* pys4 = (const float4*)pys;
    int stride = gridDim.x * 16;

    for (int s = blockIdx.x * 16 + w * 2; s < Sb; s += stride) {
        bool two = (s + 1 < Sb);
        float4 v0[8], v1[8];
        fetch_pos(s, lx, ly, b, lane, x, y, cls, sep, pxs4, pys4, v0);
        if (two) fetch_pos(s + 1, lx, ly, b, lane, x, y, cls, sep, pxs4, pys4, v1);

        float acc0[NH], acc1[NH];
        #pragma unroll
        for (int h = 0; h < NH; h++) {
            float a0 = 0.f, a1 = 0.f;
            const float4* q4 = qh4 + h * 256;
            #pragma unroll
            for (int k = 0; k < 8; k++) {
                float4 qv = q4[lane + 32 * k];
                a0 += qv.x * v0[k].x + qv.y * v0[k].y + qv.z * v0[k].z + qv.w * v0[k].w;
                if (two)
                    a1 += qv.x * v1[k].x + qv.y * v1[k].y + qv.z * v1[k].z + qv.w * v1[k].w;
            }
            acc0[h] = a0; acc1[h] = a1;
        }
        #pragma unroll
        for (int h = 0; h < NH; h++) {
            #pragma unroll
            for (int o = 16; o; o >>= 1) {
                acc0[h] += __shfl_xor_sync(0xffffffffu, acc0[h], o);
                acc1[h] += __shfl_xor_sync(0xffffffffu, acc1[h], o);
            }
        }
        if (lane == 0) {
            #pragma unroll
            for (int h = 0; h < NH; h++) {
                float* sp = g_scores + ((size_t)b * NH + h) * SP + s;
                sp[0] = (acc0[h] + qbs[h]) * 0.125f;
                if (two) sp[1] = (acc1[h] + qbs[h]) * 0.125f;
            }
        }
    }
}

// ---------- ctx partials with LOCAL softmax stats (flash): grid (NC,2,BB) ---------
#define ROWU 512
__global__ void __launch_bounds__(256) k_ctx(
        const float* __restrict__ x, const float* __restrict__ y,
        const float* __restrict__ cls, const float* __restrict__ sep,
        const float* __restrict__ px, const float* __restrict__ py,
        const int* __restrict__ x_len, const int* __restrict__ y_len) {
    int c  = blockIdx.x;
    int dq = blockIdx.y;
    int b  = blockIdx.z;
    int t  = threadIdx.x;
    int d2 = dq * 256 + t;
    int lx = x_len[b], ly = y_len[b];
    int Sb = lx + ly + 3;
    int cl = (Sb + NC - 1) / NC;
    int s0 = c * cl, s1 = min(s0 + cl, Sb);
    int n  = s1 - s0;

    if (n <= 0) {
        #pragma unroll
        for (int h = 0; h < NH; h++)
            ((ull*)(g_ctxp + (((size_t)b * NC + c) * NH + h) * DD))[d2] = 0ull;
        if (dq == 0 && t < NH) {
            g_cstat[((b * NC + c) * NH + t) * 2]     = -1e30f;
            g_cstat[((b * NC + c) * NH + t) * 2 + 1] = 0.f;
        }
        return;
    }

    __shared__ ull a2[NH][36];
    __shared__ float lm[NH];
    if (t < NH) {
        int h = t;
        const float* sc = g_scores + ((size_t)b * NH + h) * SP + s0;
        float m = -1e30f;
        for (int ss = 0; ss < n; ss++) m = fmaxf(m, sc[ss]);
        float sum = 0.f;
        for (int ss = 0; ss < n; ss++) sum += __expf(sc[ss] - m);
        lm[h] = m;
        if (dq == 0) {
            g_cstat[((b * NC + c) * NH + h) * 2]     = m;
            g_cstat[((b * NC + c) * NH + h) * 2 + 1] = sum;
        }
    }
    __syncthreads();
    for (int i = t; i < n * NH; i += 256) {
        int h = i & 15, ss = i >> 4;
        a2[h][ss] = pack2same(__expf(g_scores[((size_t)b * NH + h) * SP + s0 + ss] - lm[h]));
    }
    __syncthreads();

    ull acc[NH];
    #pragma unroll
    for (int h = 0; h < NH; h++) acc[h] = 0ull;

    if (s0 == 0) {
        ull cv = ((const ull*)cls)[d2];
        #pragma unroll
        for (int h = 0; h < NH; h++) FMA2(acc[h], a2[h][0], cv);
    }
    {
        int p0 = max(s0, 1), p1 = min(s1, lx + 1);
        if (p0 < p1) {
            ull pxv = ((const ull*)px)[d2];
            const ull* xp = (const ull*)x + ((size_t)b * 512 + (p0 - 1)) * ROWU + d2;
            int nn = p1 - p0, base = p0 - s0;
            int s = 0;
            for (; s + 2 <= nn; s += 2) {
                ull r0 = xp[(size_t)s * ROWU];
                ull r1 = xp[(size_t)(s + 1) * ROWU];
                ull v0, v1;
                ADD2(v0, r0, pxv);
                ADD2(v1, r1, pxv);
                int ss = base + s;
                #pragma unroll
                for (int h = 0; h < NH; h++) {
                    FMA2(acc[h], a2[h][ss], v0);
                    FMA2(acc[h], a2[h][ss + 1], v1);
                }
            }
            if (s < nn) {
                ull r0 = xp[(size_t)s * ROWU];
                ull v0;
                ADD2(v0, r0, pxv);
                int ss = base + s;
                #pragma unroll
                for (int h = 0; h < NH; h++) FMA2(acc[h], a2[h][ss], v0);
            }
        }
    }
    {
        int sA = lx + 1, sB = lx + ly + 2;
        bool hA = (sA >= s0 && sA < s1), hB = (sB >= s0 && sB < s1);
        if (hA || hB) {
            ull sv = ((const ull*)sep)[d2];
            if (hA) {
                #pragma unroll
                for (int h = 0; h < NH; h++) FMA2(acc[h], a2[h][sA - s0], sv);
            }
            if (hB) {
                #pragma unroll
                for (int h = 0; h < NH; h++) FMA2(acc[h], a2[h][sB - s0], sv);
            }
        }
    }
    {
        int p0 = max(s0, lx + 2), p1 = min(s1, lx + ly + 2);
        if (p0 < p1) {
            ull pyv = ((const ull*)py)[d2];
            const ull* yp = (const ull*)y + ((size_t)b * 512 + (p0 - lx - 2)) * ROWU + d2;
            int nn = p1 - p0, base = p0 - s0;
            int s = 0;
            for (; s + 2 <= nn; s += 2) {
                ull r0 = yp[(size_t)s * ROWU];
                ull r1 = yp[(size_t)(s + 1) * ROWU];
                ull v0, v1;
                ADD2(v0, r0, pyv);
                ADD2(v1, r1, pyv);
                int ss = base + s;
                #pragma unroll
                for (int h = 0; h < NH; h++) {
                    FMA2(acc[h], a2[h][ss], v0);
                    FMA2(acc[h], a2[h][ss + 1], v1);
                }
            }
            if (s < nn) {
                ull r0 = yp[(size_t)s * ROWU];
                ull v0;
                ADD2(v0, r0, pyv);
                int ss = base + s;
                #pragma unroll
                for (int h = 0; h < NH; h++) FMA2(acc[h], a2[h][ss], v0);
            }
        }
    }
    #pragma unroll
    for (int h = 0; h < NH; h++)
        ((ull*)(g_ctxp + (((size_t)b * NC + c) * NH + h) * DD))[d2] = acc[h];
}

// ---------- combine chunks (flash rescale): grid (BB, 32), block 256 ---------------
__global__ void k_combine() {
    int b = blockIdx.x;
    int q = blockIdx.y;
    int t = threadIdx.x;
    int half = t >> 7;
    int tt = t & 127;
    int j = q * 128 + tt;
    int h = j >> 8;
    __shared__ float wsc[NC][NH];
    __shared__ float Ms[NH], inv[NH];
    __shared__ __align__(16) float4 buf[128];

    if (t < NH) {
        float M = -1e30f;
        for (int c = 0; c < NC; c++)
            M = fmaxf(M, g_cstat[((b * NC + c) * NH + t) * 2]);
        Ms[t] = M;
    }
    __syncthreads();
    if (t < NH) {
        float den = 0.f;
        for (int c = 0; c < NC; c++)
            den += g_cstat[((b * NC + c) * NH + t) * 2 + 1] *
                   __expf(g_cstat[((b * NC + c) * NH + t) * 2] - Ms[t]);
        inv[t] = 1.f / den;
    }
    __syncthreads();
    for (int i = t; i < NC * NH; i += 256) {
        int cc = i >> 4, hh = i & 15;
        wsc[cc][hh] = __expf(g_cstat[((b * NC + cc) * NH + hh) * 2] - Ms[hh]) * inv[hh];
    }
    __syncthreads();

    float4 s = {0.f, 0.f, 0.f, 0.f};
    int c0 = half * 16;
    #pragma unroll
    for (int cc = 0; cc < 16; cc++) {
        int c = c0 + cc;
        float4 v = ((const float4*)(g_ctxp + ((size_t)b * NC + c) * (NH * DD)))[j];
        float f = wsc[c][h];
        s.x += v.x * f; s.y += v.y * f; s.z += v.z * f; s.w += v.w * f;
    }
    if (half == 1) buf[tt] = s;
    __syncthreads();
    if (half == 0) {
        float4 o = buf[tt];
        s.x += o.x; s.y += o.y; s.z += o.z; s.w += o.w;
        ((float4*)(g_ctx + (size_t)b * (NH * DD)))[j] = s;
    }
}

// ---------- split-K GEMV, no smem staging: 4 rows x 2 K-halves per block ------------
// grid = OUT/4, block 256. x via __ldg (L1-resident, 32KB total).
__global__ void __launch_bounds__(256) k_gemvS(
        const float* __restrict__ W, const float* __restrict__ xin,
        const float* __restrict__ bias, const float* __restrict__ residE,
        const float* __restrict__ residB, float* __restrict__ out,
        int IN, int OUT, int doRelu) {
    int t = threadIdx.x, w = t >> 5, lane = t & 31;
    int r = w >> 1, kh = w & 1;
    int e = blockIdx.x * 4 + r;
    int K2 = IN >> 1;
    int n4 = K2 >> 2;
    const float4* Wr = (const float4*)(W + (size_t)e * IN + kh * K2);

    float acc[BB];
    #pragma unroll
    for (int b = 0; b < BB; b++) acc[b] = 0.f;
    for (int i = lane; i < n4; i += 32) {
        float4 wv = __ldg(&Wr[i]);
        #pragma unroll
        for (int b = 0; b < BB; b++) {
            float4 xv = __ldg((const float4*)(xin + (size_t)b * IN + kh * K2) + i);
            acc[b] += wv.x * xv.x + wv.y * xv.y + wv.z * xv.z + wv.w * xv.w;
        }
    }
    #pragma unroll
    for (int b = 0; b < BB; b++) {
        #pragma unroll
        for (int o = 16; o; o >>= 1)
            acc[b] += __shfl_xor_sync(0xffffffffu, acc[b], o);
    }
    __shared__ float part[4][2][BB];
    if (lane == 0) {
        #pragma unroll
        for (int b = 0; b < BB; b++) part[r][kh][b] = acc[b];
    }
    __syncthreads();
    if (t < 4 * BB) {
        int rr = t >> 3, b = t & 7;
        int ee = blockIdx.x * 4 + rr;
        float v = part[rr][0][b] + part[rr][1][b];
        if (bias)   v += bias[ee];
        if (residE) v += residE[ee];
        if (residB) v += residB[(size_t)b * OUT + ee];
        if (doRelu) v = fmaxf(v, 0.f);
        out[(size_t)b * OUT + ee] = v;
    }
}

// ---------- split-K V projection (per-head ctx input): grid DD/4 --------------------
__global__ void __launch_bounds__(256) k_gemvVS(
        const float* __restrict__ Wqkv, const float* __restrict__ bqkv) {
    int t = threadIdx.x, w = t >> 5, lane = t & 31;
    int r = w >> 1, kh = w & 1;
    int e = blockIdx.x * 4 + r;
    int h = e >> 6;
    const float4* Wr = (const float4*)(Wqkv + (size_t)(2 * DD + e) * DD + kh * 512);

    float acc[BB];
    #pragma unroll
    for (int b = 0; b < BB; b++) acc[b] = 0.f;
    for (int i = lane; i < 128; i += 32) {
        float4 wv = __ldg(&Wr[i]);
        #pragma unroll
        for (int b = 0; b < BB; b++) {
            float4 xv = __ldg((const float4*)(g_ctx + ((size_t)b * NH + h) * DD + kh * 512) + i);
            acc[b] += wv.x * xv.x + wv.y * xv.y + wv.z * xv.z + wv.w * xv.w;
        }
    }
    #pragma unroll
    for (int b = 0; b < BB; b++) {
        #pragma unroll
        for (int o = 16; o; o >>= 1)
            acc[b] += __shfl_xor_sync(0xffffffffu, acc[b], o);
    }
    __shared__ float part[4][2][BB];
    if (lane == 0) {
        #pragma unroll
        for (int b = 0; b < BB; b++) part[r][kh][b] = acc[b];
    }
    __syncthreads();
    if (t < 4 * BB) {
        int rr = t >> 3, b = t & 7;
        int ee = blockIdx.x * 4 + rr;
        g_oattn[(size_t)b * DD + ee] = part[rr][0][b] + part[rr][1][b] + bqkv[2 * DD + ee];
    }
}

// ---------- LayerNorm ------------------------------------------------------------------
__global__ void k_ln(const float* __restrict__ in, const float* __restrict__ gamma,
                     const float* __restrict__ beta, float* __restrict__ out) {
    int b = blockIdx.x, t = threadIdx.x;  // 256
    const float* row = in + (size_t)b * DD;
    __shared__ float sred[8];
    __shared__ float smv[2];

    float s = 0.f;
    for (int i = t; i < DD; i += 256) s += row[i];
    #pragma unroll
    for (int o = 16; o; o >>= 1) s += __shfl_xor_sync(0xffffffffu, s, o);
    if ((t & 31) == 0) sred[t >> 5] = s;
    __syncthreads();
    if (t == 0) {
        float m = 0.f;
        #pragma unroll
        for (int i = 0; i < 8; i++) m += sred[i];
        smv[0] = m * (1.f / DD);
    }
    __syncthreads();
    float m = smv[0];

    float v = 0.f;
    for (int i = t; i < DD; i += 256) { float dd2 = row[i] - m; v += dd2 * dd2; }
    #pragma unroll
    for (int o = 16; o; o >>= 1) v += __shfl_xor_sync(0xffffffffu, v, o);
    __syncthreads();
    if ((t & 31) == 0) sred[t >> 5] = v;
    __syncthreads();
    if (t == 0) {
        float vv = 0.f;
        #pragma unroll
        for (int i = 0; i < 8; i++) vv += sred[i];
        smv[1] = rsqrtf(vv * (1.f / DD) + EPSL);
    }
    __syncthreads();
    float r = smv[1];
    for (int i = t; i < DD; i += 256)
        out[(size_t)b * DD + i] = (row[i] - m) * r * gamma[i] + beta[i];
}

extern "C" void kernel_launch(void* const* d_in, const int* in_sizes, int n_in,
                              void* d_out, int out_size) {
    const float* x     = (const float*)d_in[0];
    const float* y     = (const float*)d_in[1];
    const float* cls   = (const float*)d_in[2];
    const float* sep   = (const float*)d_in[3];
    const float* px    = (const float*)d_in[4];
    const float* py    = (const float*)d_in[5];
    const float* Wqkv  = (const float*)d_in[6];
    const float* bqkv  = (const float*)d_in[7];
    const float* Wo    = (const float*)d_in[8];
    const float* bo    = (const float*)d_in[9];
    const float* W1    = (const float*)d_in[10];
    const float* b1    = (const float*)d_in[11];
    const float* W2    = (const float*)d_in[12];
    const float* b2    = (const float*)d_in[13];
    const float* ln1g  = (const float*)d_in[14];
    const float* ln1b  = (const float*)d_in[15];
    const float* ln2g  = (const float*)d_in[16];
    const float* ln2b  = (const float*)d_in[17];
    const int*   x_len = (const int*)d_in[18];
    const int*   y_len = (const int*)d_in[19];
    float* outp = (float*)d_out;

    float *p_oattn, *p_ores, *p_h1, *p_f, *p_f2;
    cudaGetSymbolAddress((void**)&p_oattn, g_oattn);
    cudaGetSymbolAddress((void**)&p_ores,  g_ores);
    cudaGetSymbolAddress((void**)&p_h1,    g_h1);
    cudaGetSymbolAddress((void**)&p_f,     g_f);
    cudaGetSymbolAddress((void**)&p_f2,    g_f2);

    const int SCORES_SMEM = (NH * DD + 2 * DD + 16) * (int)sizeof(float);  // ~74KB
    cudaFuncSetAttribute(k_scores, cudaFuncAttributeMaxDynamicSharedMemorySize, SCORES_SMEM);

    k_q0qhat<<<dim3(NH, 4), 256>>>(Wqkv, bqkv, cls);
    k_scores<<<dim3(19, BB), 256, SCORES_SMEM>>>(x, y, cls, sep, px, py, x_len, y_len);
    k_ctx<<<dim3(NC, 2, BB), 256>>>(x, y, cls, sep, px, py, x_len, y_len);
    k_combine<<<dim3(BB, 32), 256>>>();
    k_gemvVS<<<DD / 4, 256>>>(Wqkv, bqkv);
    k_gemvS<<<DD / 4, 256>>>(Wo, p_oattn, bo, cls, nullptr, p_ores, DD, DD, 0);
    k_ln<<<BB, 256>>>(p_ores, ln1g, ln1b, p_h1);
    k_gemvS<<<FF / 4, 256>>>(W1, p_h1, b1, nullptr, nullptr, p_f, DD, FF, 1);
    k_gemvS<<<DD / 4, 256>>>(W2, p_f, b2, nullptr, p_h1, p_f2, FF, DD, 0);
    k_ln<<<BB, 256>>>(p_f2, ln2g, ln2b, outp);
}

// round 16
// speedup vs baseline: 1.2300x; 1.0015x over previous
#include <cuda_runtime.h>
#include <math.h>

#define DD   1024
#define NH   16
#define HDIM 64
#define FF   2048
#define BB   8
#define SP   1056
#define EPSL 1e-5f
#define NC   32

typedef unsigned long long ull;

__device__ __forceinline__ ull pack2same(float v) {
    unsigned u = __float_as_uint(v);
    return ((ull)u << 32) | u;
}
#define FMA2(d, a, b) asm("fma.rn.f32x2 %0, %1, %2, %0;" : "+l"(d) : "l"(a), "l"(b))
#define ADD2(d, a, b) asm("add.rn.f32x2 %0, %1, %2;" : "=l"(d) : "l"(a), "l"(b))

__device__ float g_scores[(size_t)BB * NH * SP];
__device__ float g_cstat[BB * NC * NH * 2];
__device__ float g_qhat[NH * DD];
__device__ float g_qb[NH];
__device__ float g_ctxp[(size_t)BB * NC * NH * DD];
__device__ float g_ctx[(size_t)BB * NH * DD];
__device__ float g_oattn[BB * DD];
__device__ float g_ores[BB * DD];
__device__ float g_h1[BB * DD];
__device__ float g_f[BB * FF];
__device__ float g_f2[BB * DD];

// ---------- q0 + qhat: grid (NH, 4) --------------------------------------------
__global__ void k_q0qhat(const float* __restrict__ Wqkv, const float* __restrict__ bqkv,
                         const float* __restrict__ cls) {
    int h = blockIdx.x, q = blockIdx.y;
    int t = threadIdx.x;                 // 256
    int w = t >> 5, lane = t & 31;
    __shared__ __align__(16) float clss[DD];
    __shared__ float q0s[HDIM];

    for (int i = t; i < DD / 4; i += 256)
        ((float4*)clss)[i] = ((const float4*)cls)[i];
    __syncthreads();

    const float4* c4 = (const float4*)clss;
    for (int jr = 0; jr < 8; jr++) {
        int j = w * 8 + jr;
        const float4* Wr = (const float4*)(Wqkv + (size_t)(h * HDIM + j) * DD);
        float acc = 0.f;
        for (int i = lane; i < DD / 4; i += 32) {
            float4 wv = Wr[i], cv = c4[i];
            acc += wv.x * cv.x + wv.y * cv.y + wv.z * cv.z + wv.w * cv.w;
        }
        #pragma unroll
        for (int o = 16; o; o >>= 1) acc += __shfl_xor_sync(0xffffffffu, acc, o);
        if (lane == 0) q0s[j] = acc + bqkv[h * HDIM + j];
    }
    __syncthreads();

    int d = q * 256 + t;
    float acc = 0.f;
    #pragma unroll 4
    for (int j = 0; j < HDIM; j++)
        acc += q0s[j] * Wqkv[(size_t)(DD + h * HDIM + j) * DD + d];
    g_qhat[h * DD + d] = acc;
    if (q == 0 && t == 0) {
        float s = 0.f;
        for (int j = 0; j < HDIM; j++) s += q0s[j] * bqkv[DD + h * HDIM + j];
        g_qb[h] = s;
    }
}

// ---------- position fetch helper -----------------------------------------------
__device__ __forceinline__ void fetch_pos(
    int s, int lx, int ly, int b, int lane,
    const float* __restrict__ x, const float* __restrict__ y,
    const float* __restrict__ cls, const float* __restrict__ sep,
    const float4* __restrict__ pxs4, const float4* __restrict__ pys4,
    float4 v[8]) {
    if (s == 0) {
        const float4* c4 = (const float4*)cls;
        #pragma unroll
        for (int k = 0; k < 8; k++) v[k] = __ldg(&c4[lane + 32 * k]);
    } else if (s <= lx) {
        const float4* xr = (const float4*)(x + ((size_t)b * 512 + (s - 1)) * DD);
        #pragma unroll
        for (int k = 0; k < 8; k++) {
            float4 a = __ldg(&xr[lane + 32 * k]), p = pxs4[lane + 32 * k];
            v[k].x = a.x + p.x; v[k].y = a.y + p.y; v[k].z = a.z + p.z; v[k].w = a.w + p.w;
        }
    } else if (s == lx + 1 || s == lx + ly + 2) {
        const float4* s4 = (const float4*)sep;
        #pragma unroll
        for (int k = 0; k < 8; k++) v[k] = __ldg(&s4[lane + 32 * k]);
    } else {
        const float4* yr = (const float4*)(y + ((size_t)b * 512 + (s - lx - 2)) * DD);
        #pragma unroll
        for (int k = 0; k < 8; k++) {
            float4 a = __ldg(&yr[lane + 32 * k]), p = pys4[lane + 32 * k];
            v[k].x = a.x + p.x; v[k].y = a.y + p.y; v[k].z = a.z + p.z; v[k].w = a.w + p.w;
        }
    }
}

// ---------- scores: 2 positions/warp, grid (19, BB) ------------------------------
__global__ void k_scores(const float* __restrict__ x, const float* __restrict__ y,
                         const float* __restrict__ cls, const float* __restrict__ sep,
                         const float* __restrict__ px, const float* __restrict__ py,
                         const int* __restrict__ x_len, const int* __restrict__ y_len) {
    extern __shared__ __align__(16) float dsm[];
    float* qh  = dsm;
    float* pxs = dsm + NH * DD;
    float* pys = pxs + DD;
    float* qbs = pys + DD;
    int b = blockIdx.y;
    int t = threadIdx.x, w = t >> 5, lane = t & 31;

    float4* qh4 = (float4*)qh;
    for (int i = t; i < NH * DD / 4; i += 256) qh4[i] = ((const float4*)g_qhat)[i];
    if (t < 256) { ((float4*)pxs)[t] = ((const float4*)px)[t]; ((float4*)pys)[t] = ((const float4*)py)[t]; }
    if (t < NH) qbs[t] = g_qb[t];
    __syncthreads();

    int lx = x_len[b], ly = y_len[b];
    int Sb = lx + ly + 3;
    const float4* pxs4 = (const float4*)pxs;
    const float4* pys4 = (const float4*)pys;
    int stride = gridDim.x * 16;

    for (int s = blockIdx.x * 16 + w * 2; s < Sb; s += stride) {
        bool two = (s + 1 < Sb);
        float4 v0[8], v1[8];
        fetch_pos(s, lx, ly, b, lane, x, y, cls, sep, pxs4, pys4, v0);
        if (two) fetch_pos(s + 1, lx, ly, b, lane, x, y, cls, sep, pxs4, pys4, v1);

        float acc0[NH], acc1[NH];
        #pragma unroll
        for (int h = 0; h < NH; h++) {
            float a0 = 0.f, a1 = 0.f;
            const float4* q4 = qh4 + h * 256;
            #pragma unroll
            for (int k = 0; k < 8; k++) {
                float4 qv = q4[lane + 32 * k];
                a0 += qv.x * v0[k].x + qv.y * v0[k].y + qv.z * v0[k].z + qv.w * v0[k].w;
                if (two)
                    a1 += qv.x * v1[k].x + qv.y * v1[k].y + qv.z * v1[k].z + qv.w * v1[k].w;
            }
            acc0[h] = a0; acc1[h] = a1;
        }
        #pragma unroll
        for (int h = 0; h < NH; h++) {
            #pragma unroll
            for (int o = 16; o; o >>= 1) {
                acc0[h] += __shfl_xor_sync(0xffffffffu, acc0[h], o);
                acc1[h] += __shfl_xor_sync(0xffffffffu, acc1[h], o);
            }
        }
        if (lane == 0) {
            #pragma unroll
            for (int h = 0; h < NH; h++) {
                float* sp = g_scores + ((size_t)b * NH + h) * SP + s;
                sp[0] = (acc0[h] + qbs[h]) * 0.125f;
                if (two) sp[1] = (acc1[h] + qbs[h]) * 0.125f;
            }
        }
    }
}

// ---------- ctx partials with LOCAL softmax stats (flash): grid (NC,2,BB) ---------
#define ROWU 512
__global__ void __launch_bounds__(256) k_ctx(
        const float* __restrict__ x, const float* __restrict__ y,
        const float* __restrict__ cls, const float* __restrict__ sep,
        const float* __restrict__ px, const float* __restrict__ py,
        const int* __restrict__ x_len, const int* __restrict__ y_len) {
    int c  = blockIdx.x;
    int dq = blockIdx.y;
    int b  = blockIdx.z;
    int t  = threadIdx.x;
    int d2 = dq * 256 + t;
    int lx = x_len[b], ly = y_len[b];
    int Sb = lx + ly + 3;
    int cl = (Sb + NC - 1) / NC;
    int s0 = c * cl, s1 = min(s0 + cl, Sb);
    int n  = s1 - s0;

    if (n <= 0) {
        #pragma unroll
        for (int h = 0; h < NH; h++)
            ((ull*)(g_ctxp + (((size_t)b * NC + c) * NH + h) * DD))[d2] = 0ull;
        if (dq == 0 && t < NH) {
            g_cstat[((b * NC + c) * NH + t) * 2]     = -1e30f;
            g_cstat[((b * NC + c) * NH + t) * 2 + 1] = 0.f;
        }
        return;
    }

    __shared__ ull a2[NH][36];
    __shared__ float lm[NH];
    if (t < NH) {
        int h = t;
        const float* sc = g_scores + ((size_t)b * NH + h) * SP + s0;
        float m = -1e30f;
        for (int ss = 0; ss < n; ss++) m = fmaxf(m, sc[ss]);
        float sum = 0.f;
        for (int ss = 0; ss < n; ss++) sum += __expf(sc[ss] - m);
        lm[h] = m;
        if (dq == 0) {
            g_cstat[((b * NC + c) * NH + h) * 2]     = m;
            g_cstat[((b * NC + c) * NH + h) * 2 + 1] = sum;
        }
    }
    __syncthreads();
    for (int i = t; i < n * NH; i += 256) {
        int h = i & 15, ss = i >> 4;
        a2[h][ss] = pack2same(__expf(g_scores[((size_t)b * NH + h) * SP + s0 + ss] - lm[h]));
    }
    __syncthreads();

    ull acc[NH];
    #pragma unroll
    for (int h = 0; h < NH; h++) acc[h] = 0ull;

    if (s0 == 0) {
        ull cv = ((const ull*)cls)[d2];
        #pragma unroll
        for (int h = 0; h < NH; h++) FMA2(acc[h], a2[h][0], cv);
    }
    {
        int p0 = max(s0, 1), p1 = min(s1, lx + 1);
        if (p0 < p1) {
            ull pxv = ((const ull*)px)[d2];
            const ull* xp = (const ull*)x + ((size_t)b * 512 + (p0 - 1)) * ROWU + d2;
            int nn = p1 - p0, base = p0 - s0;
            int s = 0;
            for (; s + 2 <= nn; s += 2) {
                ull r0 = xp[(size_t)s * ROWU];
                ull r1 = xp[(size_t)(s + 1) * ROWU];
                ull v0, v1;
                ADD2(v0, r0, pxv);
                ADD2(v1, r1, pxv);
                int ss = base + s;
                #pragma unroll
                for (int h = 0; h < NH; h++) {
                    FMA2(acc[h], a2[h][ss], v0);
                    FMA2(acc[h], a2[h][ss + 1], v1);
                }
            }
            if (s < nn) {
                ull r0 = xp[(size_t)s * ROWU];
                ull v0;
                ADD2(v0, r0, pxv);
                int ss = base + s;
                #pragma unroll
                for (int h = 0; h < NH; h++) FMA2(acc[h], a2[h][ss], v0);
            }
        }
    }
    {
        int sA = lx + 1, sB = lx + ly + 2;
        bool hA = (sA >= s0 && sA < s1), hB = (sB >= s0 && sB < s1);
        if (hA || hB) {
            ull sv = ((const ull*)sep)[d2];
            if (hA) {
                #pragma unroll
                for (int h = 0; h < NH; h++) FMA2(acc[h], a2[h][sA - s0], sv);
            }
            if (hB) {
                #pragma unroll
                for (int h = 0; h < NH; h++) FMA2(acc[h], a2[h][sB - s0], sv);
            }
        }
    }
    {
        int p0 = max(s0, lx + 2), p1 = min(s1, lx + ly + 2);
        if (p0 < p1) {
            ull pyv = ((const ull*)py)[d2];
            const ull* yp = (const ull*)y + ((size_t)b * 512 + (p0 - lx - 2)) * ROWU + d2;
            int nn = p1 - p0, base = p0 - s0;
            int s = 0;
            for (; s + 2 <= nn; s += 2) {
                ull r0 = yp[(size_t)s * ROWU];
                ull r1 = yp[(size_t)(s + 1) * ROWU];
                ull v0, v1;
                ADD2(v0, r0, pyv);
                ADD2(v1, r1, pyv);
                int ss = base + s;
                #pragma unroll
                for (int h = 0; h < NH; h++) {
                    FMA2(acc[h], a2[h][ss], v0);
                    FMA2(acc[h], a2[h][ss + 1], v1);
                }
            }
            if (s < nn) {
                ull r0 = yp[(size_t)s * ROWU];
                ull v0;
                ADD2(v0, r0, pyv);
                int ss = base + s;
                #pragma unroll
                for (int h = 0; h < NH; h++) FMA2(acc[h], a2[h][ss], v0);
            }
        }
    }
    #pragma unroll
    for (int h = 0; h < NH; h++)
        ((ull*)(g_ctxp + (((size_t)b * NC + c) * NH + h) * DD))[d2] = acc[h];
}

// ---------- combine chunks (flash rescale), MLP=8 batched loads -------------------
__global__ void __launch_bounds__(256) k_combine() {
    int b = blockIdx.x;
    int q = blockIdx.y;            // 0..31
    int t = threadIdx.x;           // 256
    int half = t >> 7;             // chunk half 0/1
    int tt = t & 127;
    int j = q * 128 + tt;          // float4 index over NH*DD/4 = 4096
    int h = j >> 8;
    __shared__ float wsc[NC][NH];
    __shared__ float Ms[NH], inv[NH];
    __shared__ __align__(16) float4 buf[128];

    if (t < NH) {
        float M = -1e30f;
        #pragma unroll
        for (int c = 0; c < NC; c++)
            M = fmaxf(M, g_cstat[((b * NC + c) * NH + t) * 2]);
        Ms[t] = M;
    }
    __syncthreads();
    if (t < NH) {
        float den = 0.f;
        #pragma unroll
        for (int c = 0; c < NC; c++)
            den += g_cstat[((b * NC + c) * NH + t) * 2 + 1] *
                   __expf(g_cstat[((b * NC + c) * NH + t) * 2] - Ms[t]);
        inv[t] = 1.f / den;
    }
    __syncthreads();
    for (int i = t; i < NC * NH; i += 256) {
        int cc = i >> 4, hh = i & 15;
        wsc[cc][hh] = __expf(g_cstat[((b * NC + cc) * NH + hh) * 2] - Ms[hh]) * inv[hh];
    }
    __syncthreads();

    float4 s = {0.f, 0.f, 0.f, 0.f};
    int c0 = half * 16;
    #pragma unroll
    for (int cc = 0; cc < 16; cc += 8) {
        float4 vv[8];
        float  ff[8];
        #pragma unroll
        for (int u = 0; u < 8; u++) {
            int c = c0 + cc + u;
            vv[u] = __ldg((const float4*)(g_ctxp + ((size_t)b * NC + c) * (NH * DD)) + j);
            ff[u] = wsc[c][h];
        }
        #pragma unroll
        for (int u = 0; u < 8; u++) {
            s.x += vv[u].x * ff[u]; s.y += vv[u].y * ff[u];
            s.z += vv[u].z * ff[u]; s.w += vv[u].w * ff[u];
        }
    }
    if (half == 1) buf[tt] = s;
    __syncthreads();
    if (half == 0) {
        float4 o = buf[tt];
        s.x += o.x; s.y += o.y; s.z += o.z; s.w += o.w;
        ((float4*)(g_ctx + (size_t)b * (NH * DD)))[j] = s;
    }
}

// ---------- split-K GEMV, no smem staging ------------------------------------------
__global__ void __launch_bounds__(256) k_gemvS(
        const float* __restrict__ W, const float* __restrict__ xin,
        const float* __restrict__ bias, const float* __restrict__ residE,
        const float* __restrict__ residB, float* __restrict__ out,
        int IN, int OUT, int doRelu) {
    int t = threadIdx.x, w = t >> 5, lane = t & 31;
    int r = w >> 1, kh = w & 1;
    int e = blockIdx.x * 4 + r;
    int K2 = IN >> 1;
    int n4 = K2 >> 2;
    const float4* Wr = (const float4*)(W + (size_t)e * IN + kh * K2);

    float acc[BB];
    #pragma unroll
    for (int b = 0; b < BB; b++) acc[b] = 0.f;
    for (int i = lane; i < n4; i += 32) {
        float4 wv = __ldg(&Wr[i]);
        #pragma unroll
        for (int b = 0; b < BB; b++) {
            float4 xv = __ldg((const float4*)(xin + (size_t)b * IN + kh * K2) + i);
            acc[b] += wv.x * xv.x + wv.y * xv.y + wv.z * xv.z + wv.w * xv.w;
        }
    }
    #pragma unroll
    for (int b = 0; b < BB; b++) {
        #pragma unroll
        for (int o = 16; o; o >>= 1)
            acc[b] += __shfl_xor_sync(0xffffffffu, acc[b], o);
    }
    __shared__ float part[4][2][BB];
    if (lane == 0) {
        #pragma unroll
        for (int b = 0; b < BB; b++) part[r][kh][b] = acc[b];
    }
    __syncthreads();
    if (t < 4 * BB) {
        int rr = t >> 3, b = t & 7;
        int ee = blockIdx.x * 4 + rr;
        float v = part[rr][0][b] + part[rr][1][b];
        if (bias)   v += bias[ee];
        if (residE) v += residE[ee];
        if (residB) v += residB[(size_t)b * OUT + ee];
        if (doRelu) v = fmaxf(v, 0.f);
        out[(size_t)b * OUT + ee] = v;
    }
}

// ---------- split-K V projection (per-head ctx input) --------------------------------
__global__ void __launch_bounds__(256) k_gemvVS(
        const float* __restrict__ Wqkv, const float* __restrict__ bqkv) {
    int t = threadIdx.x, w = t >> 5, lane = t & 31;
    int r = w >> 1, kh = w & 1;
    int e = blockIdx.x * 4 + r;
    int h = e >> 6;
    const float4* Wr = (const float4*)(Wqkv + (size_t)(2 * DD + e) * DD + kh * 512);

    float acc[BB];
    #pragma unroll
    for (int b = 0; b < BB; b++) acc[b] = 0.f;
    for (int i = lane; i < 128; i += 32) {
        float4 wv = __ldg(&Wr[i]);
        #pragma unroll
        for (int b = 0; b < BB; b++) {
            float4 xv = __ldg((const float4*)(g_ctx + ((size_t)b * NH + h) * DD + kh * 512) + i);
            acc[b] += wv.x * xv.x + wv.y * xv.y + wv.z * xv.z + wv.w * xv.w;
        }
    }
    #pragma unroll
    for (int b = 0; b < BB; b++) {
        #pragma unroll
        for (int o = 16; o; o >>= 1)
            acc[b] += __shfl_xor_sync(0xffffffffu, acc[b], o);
    }
    __shared__ float part[4][2][BB];
    if (lane == 0) {
        #pragma unroll
        for (int b = 0; b < BB; b++) part[r][kh][b] = acc[b];
    }
    __syncthreads();
    if (t < 4 * BB) {
        int rr = t >> 3, b = t & 7;
        int ee = blockIdx.x * 4 + rr;
        g_oattn[(size_t)b * DD + ee] = part[rr][0][b] + part[rr][1][b] + bqkv[2 * DD + ee];
    }
}

// ---------- LayerNorm ------------------------------------------------------------------
__global__ void k_ln(const float* __restrict__ in, const float* __restrict__ gamma,
                     const float* __restrict__ beta, float* __restrict__ out) {
    int b = blockIdx.x, t = threadIdx.x;  // 256
    const float* row = in + (size_t)b * DD;
    __shared__ float sred[8];
    __shared__ float smv[2];

    float s = 0.f;
    for (int i = t; i < DD; i += 256) s += row[i];
    #pragma unroll
    for (int o = 16; o; o >>= 1) s += __shfl_xor_sync(0xffffffffu, s, o);
    if ((t & 31) == 0) sred[t >> 5] = s;
    __syncthreads();
    if (t == 0) {
        float m = 0.f;
        #pragma unroll
        for (int i = 0; i < 8; i++) m += sred[i];
        smv[0] = m * (1.f / DD);
    }
    __syncthreads();
    float m = smv[0];

    float v = 0.f;
    for (int i = t; i < DD; i += 256) { float dd2 = row[i] - m; v += dd2 * dd2; }
    #pragma unroll
    for (int o = 16; o; o >>= 1) v += __shfl_xor_sync(0xffffffffu, v, o);
    __syncthreads();
    if ((t & 31) == 0) sred[t >> 5] = v;
    __syncthreads();
    if (t == 0) {
        float vv = 0.f;
        #pragma unroll
        for (int i = 0; i < 8; i++) vv += sred[i];
        smv[1] = rsqrtf(vv * (1.f / DD) + EPSL);
    }
    __syncthreads();
    float r = smv[1];
    for (int i = t; i < DD; i += 256)
        out[(size_t)b * DD + i] = (row[i] - m) * r * gamma[i] + beta[i];
}

extern "C" void kernel_launch(void* const* d_in, const int* in_sizes, int n_in,
                              void* d_out, int out_size) {
    const float* x     = (const float*)d_in[0];
    const float* y     = (const float*)d_in[1];
    const float* cls   = (const float*)d_in[2];
    const float* sep   = (const float*)d_in[3];
    const float* px    = (const float*)d_in[4];
    const float* py    = (const float*)d_in[5];
    const float* Wqkv  = (const float*)d_in[6];
    const float* bqkv  = (const float*)d_in[7];
    const float* Wo    = (const float*)d_in[8];
    const float* bo    = (const float*)d_in[9];
    const float* W1    = (const float*)d_in[10];
    const float* b1    = (const float*)d_in[11];
    const float* W2    = (const float*)d_in[12];
    const float* b2    = (const float*)d_in[13];
    const float* ln1g  = (const float*)d_in[14];
    const float* ln1b  = (const float*)d_in[15];
    const float* ln2g  = (const float*)d_in[16];
    const float* ln2b  = (const float*)d_in[17];
    const int*   x_len = (const int*)d_in[18];
    const int*   y_len = (const int*)d_in[19];
    float* outp = (float*)d_out;

    float *p_oattn, *p_ores, *p_h1, *p_f, *p_f2;
    cudaGetSymbolAddress((void**)&p_oattn, g_oattn);
    cudaGetSymbolAddress((void**)&p_ores,  g_ores);
    cudaGetSymbolAddress((void**)&p_h1,    g_h1);
    cudaGetSymbolAddress((void**)&p_f,     g_f);
    cudaGetSymbolAddress((void**)&p_f2,    g_f2);

    const int SCORES_SMEM = (NH * DD + 2 * DD + 16) * (int)sizeof(float);  // ~74KB
    cudaFuncSetAttribute(k_scores, cudaFuncAttributeMaxDynamicSharedMemorySize, SCORES_SMEM);

    k_q0qhat<<<dim3(NH, 4), 256>>>(Wqkv, bqkv, cls);
    k_scores<<<dim3(19, BB), 256, SCORES_SMEM>>>(x, y, cls, sep, px, py, x_len, y_len);
    k_ctx<<<dim3(NC, 2, BB), 256>>>(x, y, cls, sep, px, py, x_len, y_len);
    k_combine<<<dim3(BB, 32), 256>>>();
    k_gemvVS<<<DD / 4, 256>>>(Wqkv, bqkv);
    k_gemvS<<<DD / 4, 256>>>(Wo, p_oattn, bo, cls, nullptr, p_ores, DD, DD, 0);
    k_ln<<<BB, 256>>>(p_ores, ln1g, ln1b, p_h1);
    k_gemvS<<<FF / 4, 256>>>(W1, p_h1, b1, nullptr, nullptr, p_f, DD, FF, 1);
    k_gemvS<<<DD / 4, 256>>>(W2, p_f, b2, nullptr, p_h1, p_f2, FF, DD, 0);
    k_ln<<<BB, 256>>>(p_f2, ln2g, ln2b, outp);
}

// round 17
// speedup vs baseline: 1.2544x; 1.0198x over previous
#include <cuda_runtime.h>
#include <math.h>

#define DD   1024
#define NH   16
#define HDIM 64
#define FF   2048
#define BB   8
#define SP   1056
#define EPSL 1e-5f
#define NC   32

typedef unsigned long long ull;

__device__ __forceinline__ ull pack2same(float v) {
    unsigned u = __float_as_uint(v);
    return ((ull)u << 32) | u;
}
#define FMA2(d, a, b) asm("fma.rn.f32x2 %0, %1, %2, %0;" : "+l"(d) : "l"(a), "l"(b))
#define ADD2(d, a, b) asm("add.rn.f32x2 %0, %1, %2;" : "=l"(d) : "l"(a), "l"(b))

__device__ float g_scores[(size_t)BB * NH * SP];
__device__ float g_cstat[BB * NC * NH * 2];
__device__ float g_qhat[NH * DD];
__device__ float g_qb[NH];
__device__ float g_ctxp[(size_t)BB * NC * NH * DD];
__device__ float g_ctx[(size_t)BB * NH * DD];
__device__ float g_oattn[BB * DD];
__device__ float g_ores[BB * DD];
__device__ float g_h1[BB * DD];
__device__ float g_f[BB * FF];
__device__ float g_f2[BB * DD];

// ---------- q0 + qhat: grid (NH, 4) --------------------------------------------
__global__ void k_q0qhat(const float* __restrict__ Wqkv, const float* __restrict__ bqkv,
                         const float* __restrict__ cls) {
    int h = blockIdx.x, q = blockIdx.y;
    int t = threadIdx.x;                 // 256
    int w = t >> 5, lane = t & 31;
    __shared__ __align__(16) float clss[DD];
    __shared__ float q0s[HDIM];

    for (int i = t; i < DD / 4; i += 256)
        ((float4*)clss)[i] = ((const float4*)cls)[i];
    __syncthreads();

    const float4* c4 = (const float4*)clss;
    for (int jr = 0; jr < 8; jr++) {
        int j = w * 8 + jr;
        const float4* Wr = (const float4*)(Wqkv + (size_t)(h * HDIM + j) * DD);
        float acc = 0.f;
        for (int i = lane; i < DD / 4; i += 32) {
            float4 wv = Wr[i], cv = c4[i];
            acc += wv.x * cv.x + wv.y * cv.y + wv.z * cv.z + wv.w * cv.w;
        }
        #pragma unroll
        for (int o = 16; o; o >>= 1) acc += __shfl_xor_sync(0xffffffffu, acc, o);
        if (lane == 0) q0s[j] = acc + bqkv[h * HDIM + j];
    }
    __syncthreads();

    int d = q * 256 + t;
    float acc = 0.f;
    #pragma unroll 4
    for (int j = 0; j < HDIM; j++)
        acc += q0s[j] * Wqkv[(size_t)(DD + h * HDIM + j) * DD + d];
    g_qhat[h * DD + d] = acc;
    if (q == 0 && t == 0) {
        float s = 0.f;
        for (int j = 0; j < HDIM; j++) s += q0s[j] * bqkv[DD + h * HDIM + j];
        g_qb[h] = s;
    }
}

// ---------- position fetch helper -----------------------------------------------
__device__ __forceinline__ void fetch_pos(
    int s, int lx, int ly, int b, int lane,
    const float* __restrict__ x, const float* __restrict__ y,
    const float* __restrict__ cls, const float* __restrict__ sep,
    const float4* __restrict__ pxs4, const float4* __restrict__ pys4,
    float4 v[8]) {
    if (s == 0) {
        const float4* c4 = (const float4*)cls;
        #pragma unroll
        for (int k = 0; k < 8; k++) v[k] = __ldg(&c4[lane + 32 * k]);
    } else if (s <= lx) {
        const float4* xr = (const float4*)(x + ((size_t)b * 512 + (s - 1)) * DD);
        #pragma unroll
        for (int k = 0; k < 8; k++) {
            float4 a = __ldg(&xr[lane + 32 * k]), p = pxs4[lane + 32 * k];
            v[k].x = a.x + p.x; v[k].y = a.y + p.y; v[k].z = a.z + p.z; v[k].w = a.w + p.w;
        }
    } else if (s == lx + 1 || s == lx + ly + 2) {
        const float4* s4 = (const float4*)sep;
        #pragma unroll
        for (int k = 0; k < 8; k++) v[k] = __ldg(&s4[lane + 32 * k]);
    } else {
        const float4* yr = (const float4*)(y + ((size_t)b * 512 + (s - lx - 2)) * DD);
        #pragma unroll
        for (int k = 0; k < 8; k++) {
            float4 a = __ldg(&yr[lane + 32 * k]), p = pys4[lane + 32 * k];
            v[k].x = a.x + p.x; v[k].y = a.y + p.y; v[k].z = a.z + p.z; v[k].w = a.w + p.w;
        }
    }
}

// ---------- scores: 2 positions/warp, grid (38, BB) ------------------------------
__global__ void k_scores(const float* __restrict__ x, const float* __restrict__ y,
                         const float* __restrict__ cls, const float* __restrict__ sep,
                         const float* __restrict__ px, const float* __restrict__ py,
                         const int* __restrict__ x_len, const int* __restrict__ y_len) {
    extern __shared__ __align__(16) float dsm[];
    float* qh  = dsm;
    float* pxs = dsm + NH * DD;
    float* pys = pxs + DD;
    float* qbs = pys + DD;
    int b = blockIdx.y;
    int t = threadIdx.x, w = t >> 5, lane = t & 31;

    float4* qh4 = (float4*)qh;
    for (int i = t; i < NH * DD / 4; i += 256) qh4[i] = ((const float4*)g_qhat)[i];
    if (t < 256) { ((float4*)pxs)[t] = ((const float4*)px)[t]; ((float4*)pys)[t] = ((const float4*)py)[t]; }
    if (t < NH) qbs[t] = g_qb[t];
    __syncthreads();

    int lx = x_len[b], ly = y_len[b];
    int Sb = lx + ly + 3;
    const float4* pxs4 = (const float4*)pxs;
    const float4* pys4 = (const float4*)pys;
    int stride = gridDim.x * 16;

    for (int s = blockIdx.x * 16 + w * 2; s < Sb; s += stride) {
        bool two = (s + 1 < Sb);
        float4 v0[8], v1[8];
        fetch_pos(s, lx, ly, b, lane, x, y, cls, sep, pxs4, pys4, v0);
        if (two) fetch_pos(s + 1, lx, ly, b, lane, x, y, cls, sep, pxs4, pys4, v1);

        float acc0[NH], acc1[NH];
        #pragma unroll
        for (int h = 0; h < NH; h++) {
            float a0 = 0.f, a1 = 0.f;
            const float4* q4 = qh4 + h * 256;
            #pragma unroll
            for (int k = 0; k < 8; k++) {
                float4 qv = q4[lane + 32 * k];
                a0 += qv.x * v0[k].x + qv.y * v0[k].y + qv.z * v0[k].z + qv.w * v0[k].w;
                if (two)
                    a1 += qv.x * v1[k].x + qv.y * v1[k].y + qv.z * v1[k].z + qv.w * v1[k].w;
            }
            acc0[h] = a0; acc1[h] = a1;
        }
        #pragma unroll
        for (int h = 0; h < NH; h++) {
            #pragma unroll
            for (int o = 16; o; o >>= 1) {
                acc0[h] += __shfl_xor_sync(0xffffffffu, acc0[h], o);
                acc1[h] += __shfl_xor_sync(0xffffffffu, acc1[h], o);
            }
        }
        if (lane == 0) {
            #pragma unroll
            for (int h = 0; h < NH; h++) {
                float* sp = g_scores + ((size_t)b * NH + h) * SP + s;
                sp[0] = (acc0[h] + qbs[h]) * 0.125f;
                if (two) sp[1] = (acc1[h] + qbs[h]) * 0.125f;
            }
        }
    }
}

// ---------- ctx partials with LOCAL softmax stats (flash): grid (NC,2,BB) ---------
#define ROWU 512
__global__ void __launch_bounds__(256) k_ctx(
        const float* __restrict__ x, const float* __restrict__ y,
        const float* __restrict__ cls, const float* __restrict__ sep,
        const float* __restrict__ px, const float* __restrict__ py,
        const int* __restrict__ x_len, const int* __restrict__ y_len) {
    int c  = blockIdx.x;
    int dq = blockIdx.y;
    int b  = blockIdx.z;
    int t  = threadIdx.x;
    int d2 = dq * 256 + t;
    int lx = x_len[b], ly = y_len[b];
    int Sb = lx + ly + 3;
    int cl = (Sb + NC - 1) / NC;
    int s0 = c * cl, s1 = min(s0 + cl, Sb);
    int n  = s1 - s0;

    if (n <= 0) {
        #pragma unroll
        for (int h = 0; h < NH; h++)
            ((ull*)(g_ctxp + (((size_t)b * NC + c) * NH + h) * DD))[d2] = 0ull;
        if (dq == 0 && t < NH) {
            g_cstat[((b * NC + c) * NH + t) * 2]     = -1e30f;
            g_cstat[((b * NC + c) * NH + t) * 2 + 1] = 0.f;
        }
        return;
    }

    __shared__ ull a2[NH][36];
    __shared__ float lm[NH];
    if (t < NH) {
        int h = t;
        const float* sc = g_scores + ((size_t)b * NH + h) * SP + s0;
        float m = -1e30f;
        for (int ss = 0; ss < n; ss++) m = fmaxf(m, sc[ss]);
        float sum = 0.f;
        for (int ss = 0; ss < n; ss++) sum += __expf(sc[ss] - m);
        lm[h] = m;
        if (dq == 0) {
            g_cstat[((b * NC + c) * NH + h) * 2]     = m;
            g_cstat[((b * NC + c) * NH + h) * 2 + 1] = sum;
        }
    }
    __syncthreads();
    for (int i = t; i < n * NH; i += 256) {
        int h = i & 15, ss = i >> 4;
        a2[h][ss] = pack2same(__expf(g_scores[((size_t)b * NH + h) * SP + s0 + ss] - lm[h]));
    }
    __syncthreads();

    ull acc[NH];
    #pragma unroll
    for (int h = 0; h < NH; h++) acc[h] = 0ull;

    if (s0 == 0) {
        ull cv = ((const ull*)cls)[d2];
        #pragma unroll
        for (int h = 0; h < NH; h++) FMA2(acc[h], a2[h][0], cv);
    }
    {
        int p0 = max(s0, 1), p1 = min(s1, lx + 1);
        if (p0 < p1) {
            ull pxv = ((const ull*)px)[d2];
            const ull* xp = (const ull*)x + ((size_t)b * 512 + (p0 - 1)) * ROWU + d2;
            int nn = p1 - p0, base = p0 - s0;
            int s = 0;
            for (; s + 2 <= nn; s += 2) {
                ull r0 = xp[(size_t)s * ROWU];
                ull r1 = xp[(size_t)(s + 1) * ROWU];
                ull v0, v1;
                ADD2(v0, r0, pxv);
                ADD2(v1, r1, pxv);
                int ss = base + s;
                #pragma unroll
                for (int h = 0; h < NH; h++) {
                    FMA2(acc[h], a2[h][ss], v0);
                    FMA2(acc[h], a2[h][ss + 1], v1);
                }
            }
            if (s < nn) {
                ull r0 = xp[(size_t)s * ROWU];
                ull v0;
                ADD2(v0, r0, pxv);
                int ss = base + s;
                #pragma unroll
                for (int h = 0; h < NH; h++) FMA2(acc[h], a2[h][ss], v0);
            }
        }
    }
    {
        int sA = lx + 1, sB = lx + ly + 2;
        bool hA = (sA >= s0 && sA < s1), hB = (sB >= s0 && sB < s1);
        if (hA || hB) {
            ull sv = ((const ull*)sep)[d2];
            if (hA) {
                #pragma unroll
                for (int h = 0; h < NH; h++) FMA2(acc[h], a2[h][sA - s0], sv);
            }
            if (hB) {
                #pragma unroll
                for (int h = 0; h < NH; h++) FMA2(acc[h], a2[h][sB - s0], sv);
            }
        }
    }
    {
        int p0 = max(s0, lx + 2), p1 = min(s1, lx + ly + 2);
        if (p0 < p1) {
            ull pyv = ((const ull*)py)[d2];
            const ull* yp = (const ull*)y + ((size_t)b * 512 + (p0 - lx - 2)) * ROWU + d2;
            int nn = p1 - p0, base = p0 - s0;
            int s = 0;
            for (; s + 2 <= nn; s += 2) {
                ull r0 = yp[(size_t)s * ROWU];
                ull r1 = yp[(size_t)(s + 1) * ROWU];
                ull v0, v1;
                ADD2(v0, r0, pyv);
                ADD2(v1, r1, pyv);
                int ss = base + s;
                #pragma unroll
                for (int h = 0; h < NH; h++) {
                    FMA2(acc[h], a2[h][ss], v0);
                    FMA2(acc[h], a2[h][ss + 1], v1);
                }
            }
            if (s < nn) {
                ull r0 = yp[(size_t)s * ROWU];
                ull v0;
                ADD2(v0, r0, pyv);
                int ss = base + s;
                #pragma unroll
                for (int h = 0; h < NH; h++) FMA2(acc[h], a2[h][ss], v0);
            }
        }
    }
    #pragma unroll
    for (int h = 0; h < NH; h++)
        ((ull*)(g_ctxp + (((size_t)b * NC + c) * NH + h) * DD))[d2] = acc[h];
}

// ---------- combine chunks: 4 groups x 8 chunks, block 512, grid (BB, 32) ----------
__global__ void __launch_bounds__(512) k_combine() {
    int b = blockIdx.x;
    int q = blockIdx.y;            // 0..31
    int t = threadIdx.x;           // 512
    int g = t >> 7;                // chunk group 0..3
    int tt = t & 127;
    int j = q * 128 + tt;          // float4 index over NH*DD/4 = 4096
    int h = j >> 8;
    __shared__ float wsc[NC][NH];
    __shared__ float Ms[NH], inv[NH];
    __shared__ __align__(16) float4 buf[3][128];

    if (t < NH) {
        float M = -1e30f;
        #pragma unroll
        for (int c = 0; c < NC; c++)
            M = fmaxf(M, g_cstat[((b * NC + c) * NH + t) * 2]);
        Ms[t] = M;
    }
    __syncthreads();
    if (t < NH) {
        float den = 0.f;
        #pragma unroll
        for (int c = 0; c < NC; c++)
            den += g_cstat[((b * NC + c) * NH + t) * 2 + 1] *
                   __expf(g_cstat[((b * NC + c) * NH + t) * 2] - Ms[t]);
        inv[t] = 1.f / den;
    }
    __syncthreads();
    for (int i = t; i < NC * NH; i += 512) {
        int cc = i >> 4, hh = i & 15;
        wsc[cc][hh] = __expf(g_cstat[((b * NC + cc) * NH + hh) * 2] - Ms[hh]) * inv[hh];
    }
    __syncthreads();

    float4 s = {0.f, 0.f, 0.f, 0.f};
    int c0 = g * 8;
    #pragma unroll
    for (int u = 0; u < 8; u++) {
        int c = c0 + u;
        float4 v = __ldg((const float4*)(g_ctxp + ((size_t)b * NC + c) * (NH * DD)) + j);
        float f = wsc[c][h];
        s.x += v.x * f; s.y += v.y * f; s.z += v.z * f; s.w += v.w * f;
    }
    if (g > 0) buf[g - 1][tt] = s;
    __syncthreads();
    if (g == 0) {
        #pragma unroll
        for (int r = 0; r < 3; r++) {
            float4 o = buf[r][tt];
            s.x += o.x; s.y += o.y; s.z += o.z; s.w += o.w;
        }
        ((float4*)(g_ctx + (size_t)b * (NH * DD)))[j] = s;
    }
}

// ---------- split-K GEMV, no smem staging ------------------------------------------
__global__ void __launch_bounds__(256) k_gemvS(
        const float* __restrict__ W, const float* __restrict__ xin,
        const float* __restrict__ bias, const float* __restrict__ residE,
        const float* __restrict__ residB, float* __restrict__ out,
        int IN, int OUT, int doRelu) {
    int t = threadIdx.x, w = t >> 5, lane = t & 31;
    int r = w >> 1, kh = w & 1;
    int e = blockIdx.x * 4 + r;
    int K2 = IN >> 1;
    int n4 = K2 >> 2;
    const float4* Wr = (const float4*)(W + (size_t)e * IN + kh * K2);

    float acc[BB];
    #pragma unroll
    for (int b = 0; b < BB; b++) acc[b] = 0.f;
    for (int i = lane; i < n4; i += 32) {
        float4 wv = __ldg(&Wr[i]);
        #pragma unroll
        for (int b = 0; b < BB; b++) {
            float4 xv = __ldg((const float4*)(xin + (size_t)b * IN + kh * K2) + i);
            acc[b] += wv.x * xv.x + wv.y * xv.y + wv.z * xv.z + wv.w * xv.w;
        }
    }
    #pragma unroll
    for (int b = 0; b < BB; b++) {
        #pragma unroll
        for (int o = 16; o; o >>= 1)
            acc[b] += __shfl_xor_sync(0xffffffffu, acc[b], o);
    }
    __shared__ float part[4][2][BB];
    if (lane == 0) {
        #pragma unroll
        for (int b = 0; b < BB; b++) part[r][kh][b] = acc[b];
    }
    __syncthreads();
    if (t < 4 * BB) {
        int rr = t >> 3, b = t & 7;
        int ee = blockIdx.x * 4 + rr;
        float v = part[rr][0][b] + part[rr][1][b];
        if (bias)   v += bias[ee];
        if (residE) v += residE[ee];
        if (residB) v += residB[(size_t)b * OUT + ee];
        if (doRelu) v = fmaxf(v, 0.f);
        out[(size_t)b * OUT + ee] = v;
    }
}

// ---------- split-K V projection (per-head ctx input) --------------------------------
__global__ void __launch_bounds__(256) k_gemvVS(
        const float* __restrict__ Wqkv, const float* __restrict__ bqkv) {
    int t = threadIdx.x, w = t >> 5, lane = t & 31;
    int r = w >> 1, kh = w & 1;
    int e = blockIdx.x * 4 + r;
    int h = e >> 6;
    const float4* Wr = (const float4*)(Wqkv + (size_t)(2 * DD + e) * DD + kh * 512);

    float acc[BB];
    #pragma unroll
    for (int b = 0; b < BB; b++) acc[b] = 0.f;
    for (int i = lane; i < 128; i += 32) {
        float4 wv = __ldg(&Wr[i]);
        #pragma unroll
        for (int b = 0; b < BB; b++) {
            float4 xv = __ldg((const float4*)(g_ctx + ((size_t)b * NH + h) * DD + kh * 512) + i);
            acc[b] += wv.x * xv.x + wv.y * xv.y + wv.z * xv.z + wv.w * xv.w;
        }
    }
    #pragma unroll
    for (int b = 0; b < BB; b++) {
        #pragma unroll
        for (int o = 16; o; o >>= 1)
            acc[b] += __shfl_xor_sync(0xffffffffu, acc[b], o);
    }
    __shared__ float part[4][2][BB];
    if (lane == 0) {
        #pragma unroll
        for (int b = 0; b < BB; b++) part[r][kh][b] = acc[b];
    }
    __syncthreads();
    if (t < 4 * BB) {
        int rr = t >> 3, b = t & 7;
        int ee = blockIdx.x * 4 + rr;
        g_oattn[(size_t)b * DD + ee] = part[rr][0][b] + part[rr][1][b] + bqkv[2 * DD + ee];
    }
}

// ---------- LayerNorm ------------------------------------------------------------------
__global__ void k_ln(const float* __restrict__ in, const float* __restrict__ gamma,
                     const float* __restrict__ beta, float* __restrict__ out) {
    int b = blockIdx.x, t = threadIdx.x;  // 256
    const float* row = in + (size_t)b * DD;
    __shared__ float sred[8];
    __shared__ float smv[2];

    float s = 0.f;
    for (int i = t; i < DD; i += 256) s += row[i];
    #pragma unroll
    for (int o = 16; o; o >>= 1) s += __shfl_xor_sync(0xffffffffu, s, o);
    if ((t & 31) == 0) sred[t >> 5] = s;
    __syncthreads();
    if (t == 0) {
        float m = 0.f;
        #pragma unroll
        for (int i = 0; i < 8; i++) m += sred[i];
        smv[0] = m * (1.f / DD);
    }
    __syncthreads();
    float m = smv[0];

    float v = 0.f;
    for (int i = t; i < DD; i += 256) { float dd2 = row[i] - m; v += dd2 * dd2; }
    #pragma unroll
    for (int o = 16; o; o >>= 1) v += __shfl_xor_sync(0xffffffffu, v, o);
    __syncthreads();
    if ((t & 31) == 0) sred[t >> 5] = v;
    __syncthreads();
    if (t == 0) {
        float vv = 0.f;
        #pragma unroll
        for (int i = 0; i < 8; i++) vv += sred[i];
        smv[1] = rsqrtf(vv * (1.f / DD) + EPSL);
    }
    __syncthreads();
    float r = smv[1];
    for (int i = t; i < DD; i += 256)
        out[(size_t)b * DD + i] = (row[i] - m) * r * gamma[i] + beta[i];
}

extern "C" void kernel_launch(void* const* d_in, const int* in_sizes, int n_in,
                              void* d_out, int out_size) {
    const float* x     = (const float*)d_in[0];
    const float* y     = (const float*)d_in[1];
    const float* cls   = (const float*)d_in[2];
    const float* sep   = (const float*)d_in[3];
    const float* px    = (const float*)d_in[4];
    const float* py    = (const float*)d_in[5];
    const float* Wqkv  = (const float*)d_in[6];
    const float* bqkv  = (const float*)d_in[7];
    const float* Wo    = (const float*)d_in[8];
    const float* bo    = (const float*)d_in[9];
    const float* W1    = (const float*)d_in[10];
    const float* b1    = (const float*)d_in[11];
    const float* W2    = (const float*)d_in[12];
    const float* b2    = (const float*)d_in[13];
    const float* ln1g  = (const float*)d_in[14];
    const float* ln1b  = (const float*)d_in[15];
    const float* ln2g  = (const float*)d_in[16];
    const float* ln2b  = (const float*)d_in[17];
    const int*   x_len = (const int*)d_in[18];
    const int*   y_len = (const int*)d_in[19];
    float* outp = (float*)d_out;

    float *p_oattn, *p_ores, *p_h1, *p_f, *p_f2;
    cudaGetSymbolAddress((void**)&p_oattn, g_oattn);
    cudaGetSymbolAddress((void**)&p_ores,  g_ores);
    cudaGetSymbolAddress((void**)&p_h1,    g_h1);
    cudaGetSymbolAddress((void**)&p_f,     g_f);
    cudaGetSymbolAddress((void**)&p_f2,    g_f2);

    const int SCORES_SMEM = (NH * DD + 2 * DD + 16) * (int)sizeof(float);  // ~74KB
    cudaFuncSetAttribute(k_scores, cudaFuncAttributeMaxDynamicSharedMemorySize, SCORES_SMEM);

    k_q0qhat<<<dim3(NH, 4), 256>>>(Wqkv, bqkv, cls);
    k_scores<<<dim3(38, BB), 256, SCORES_SMEM>>>(x, y, cls, sep, px, py, x_len, y_len);
    k_ctx<<<dim3(NC, 2, BB), 256>>>(x, y, cls, sep, px, py, x_len, y_len);
    k_combine<<<dim3(BB, 32), 512>>>();
    k_gemvVS<<<DD / 4, 256>>>(Wqkv, bqkv);
    k_gemvS<<<DD / 4, 256>>>(Wo, p_oattn, bo, cls, nullptr, p_ores, DD, DD, 0);
    k_ln<<<BB, 256>>>(p_ores, ln1g, ln1b, p_h1);
    k_gemvS<<<FF / 4, 256>>>(W1, p_h1, b1, nullptr, nullptr, p_f, DD, FF, 1);
    k_gemvS<<<DD / 4, 256>>>(W2, p_f, b2, nullptr, p_h1, p_f2, FF, DD, 0);
    k_ln<<<BB, 256>>>(p_f2, ln2g, ln2b, outp);
}